// round 11
// baseline (speedup 1.0000x reference)
#include <cuda_runtime.h>
#include <math.h>

#define BATCH 32768
#define BM 64
#define WPITCH 72
#define WBUF (4 * 32 * WPITCH) /* 9216 uints per buffer */

__device__ __forceinline__ unsigned f2tf32(float v) {
    unsigned r;
    asm("cvt.rna.tf32.f32 %0, %1;" : "=r"(r) : "f"(v));
    return r;
}

__device__ __forceinline__ void mma8(float* d, const unsigned* a, const unsigned* b) {
    asm volatile(
        "mma.sync.aligned.m16n8k8.row.col.f32.tf32.tf32.f32 "
        "{%0,%1,%2,%3}, {%4,%5,%6,%7}, {%8,%9}, {%0,%1,%2,%3};\n"
        : "+f"(d[0]), "+f"(d[1]), "+f"(d[2]), "+f"(d[3])
        : "r"(a[0]), "r"(a[1]), "r"(a[2]), "r"(a[3]), "r"(b[0]), "r"(b[1]));
}

__device__ __forceinline__ float sigf(float x) { return 1.0f / (1.0f + __expf(-x)); }

// MODE 0: LSTM layer (4 gates f,k,i,s -> cell update, writes new_state [B,512])
// MODE 1: FF head (ni=0 means, ni=1 exp, ni=2 softmax-over-4-heads)
template <int MODE>
__global__ void __launch_bounds__(256, 1)
fused_kernel(int K, int NITER, int ni_step, int gstride, int ldw,
             const float* __restrict__ srcA, int KA, int lda,
             const float* __restrict__ srcB,
             const float* __restrict__ w0, const float* __restrict__ w1,
             const float* __restrict__ w2, const float* __restrict__ w3,
             const float* __restrict__ b0, const float* __restrict__ b1,
             const float* __restrict__ b2, const float* __restrict__ b3,
             const float* __restrict__ state_in, float* __restrict__ new_state,
             float* __restrict__ means, float* __restrict__ devs,
             float* __restrict__ mult)
{
    extern __shared__ unsigned sm[];
    const int XP = K + 4;                // pad -> conflict-free A-fragment LDS
    unsigned* xs  = sm;                  // X tile: [BM][XP] tf32
    unsigned* wsm = sm + BM * XP;        // W slabs: [2][4][32][WPITCH]

    const int tid  = threadIdx.x;
    const int lane = tid & 31, wid = tid >> 5;
    const int wm = wid >> 2, wn = wid & 3;     // 2 x 4 warp grid
    const int grp = lane >> 2, qid = lane & 3;
    const long row0 = (long)blockIdx.x * BM;

    const float* wp4[4] = {w0, w1, w2, w3};

    // ---- load X tile (concat of srcA cols [0,KA) and srcB cols [KA,K)) ----
    for (int i = tid; i < BM * K; i += 256) {
        int r = i / K;
        int c = i - r * K;
        long gr = row0 + r;
        float v = (c < KA) ? srcA[gr * lda + c] : srcB[gr * 512 + (c - KA)];
        xs[r * XP + c] = f2tf32(v);
    }
    __syncthreads();

    const int NS = K >> 5;  // 32-deep k slabs

    for (int ni = 0; ni < NITER; ni++) {
        const int ncbase = ni * ni_step;

        float acc[4][2][2][4];
        #pragma unroll
        for (int g = 0; g < 4; g++)
            #pragma unroll
            for (int mt = 0; mt < 2; mt++)
                #pragma unroll
                for (int nt = 0; nt < 2; nt++)
                    #pragma unroll
                    for (int e = 0; e < 4; e++) acc[g][mt][nt][e] = 0.f;

        // cooperative W slab load: 4 gates x 32k x 64n (float4, tf32-converted)
        auto load_slab = [&](int s, int buf) {
            unsigned* dst = wsm + buf * WBUF;
            const int k0 = s * 32;
            #pragma unroll
            for (int j = 0; j < 8; j++) {
                const int g = j >> 1;           // i>>9 constant per j (tid<256)
                int i = tid + j * 256;
                int rem = i - g * 512;
                int kk = rem >> 4;
                int n4 = rem & 15;
                const float4 v = *(const float4*)(wp4[g] + (long)(k0 + kk) * ldw +
                                                  ncbase + g * gstride + n4 * 4);
                uint4 u;
                u.x = f2tf32(v.x); u.y = f2tf32(v.y);
                u.z = f2tf32(v.z); u.w = f2tf32(v.w);
                *(uint4*)(dst + g * (32 * WPITCH) + kk * WPITCH + n4 * 4) = u;
            }
        };

        load_slab(0, 0);
        __syncthreads();

        for (int s = 0; s < NS; s++) {
            const int buf = s & 1;
            if (s + 1 < NS) load_slab(s + 1, buf ^ 1);   // prefetch into other buffer
            const unsigned* wb = wsm + buf * WBUF;
            #pragma unroll
            for (int k4 = 0; k4 < 4; k4++) {
                const int kg = s * 32 + k4 * 8;
                unsigned a[2][4];
                #pragma unroll
                for (int mt = 0; mt < 2; mt++) {
                    const unsigned* xp = xs + (wm * 32 + mt * 16 + grp) * XP + kg + qid;
                    a[mt][0] = xp[0];
                    a[mt][1] = xp[8 * XP];
                    a[mt][2] = xp[4];
                    a[mt][3] = xp[8 * XP + 4];
                }
                #pragma unroll
                for (int g = 0; g < 4; g++) {
                    #pragma unroll
                    for (int nt = 0; nt < 2; nt++) {
                        const unsigned* wp = wb + g * (32 * WPITCH) +
                                             (k4 * 8 + qid) * WPITCH +
                                             wn * 16 + nt * 8 + grp;
                        unsigned bf_[2];
                        bf_[0] = wp[0];            // k = qid
                        bf_[1] = wp[4 * WPITCH];   // k = qid + 4
                        mma8(acc[g][0][nt], a[0], bf_);
                        mma8(acc[g][1][nt], a[1], bf_);
                    }
                }
            }
            __syncthreads();
        }

        // ---- epilogue ----
        if (MODE == 0) {
            #pragma unroll
            for (int mt = 0; mt < 2; mt++)
                #pragma unroll
                for (int rh = 0; rh < 2; rh++) {
                    const long gRow = row0 + wm * 32 + mt * 16 + grp + rh * 8;
                    const int e = rh * 2;
                    #pragma unroll
                    for (int nt = 0; nt < 2; nt++) {
                        const int n = ncbase + wn * 16 + nt * 8 + 2 * qid;
                        float2 vb;
                        vb = *(const float2*)&b0[n];
                        float pf0 = acc[0][mt][nt][e] + vb.x, pf1 = acc[0][mt][nt][e + 1] + vb.y;
                        vb = *(const float2*)&b1[n];
                        float pk0 = acc[1][mt][nt][e] + vb.x, pk1 = acc[1][mt][nt][e + 1] + vb.y;
                        vb = *(const float2*)&b2[n];
                        float pi0 = acc[2][mt][nt][e] + vb.x, pi1 = acc[2][mt][nt][e + 1] + vb.y;
                        vb = *(const float2*)&b3[n];
                        float ps0 = acc[3][mt][nt][e] + vb.x, ps1 = acc[3][mt][nt][e + 1] + vb.y;
                        const float2 cold = *(const float2*)&state_in[gRow * 512 + 256 + n];
                        float cn0 = sigf(pf0) * cold.x + sigf(pk0) * tanhf(pi0);
                        float cn1 = sigf(pf1) * cold.y + sigf(pk1) * tanhf(pi1);
                        float o0 = sigf(ps0) * tanhf(cn0);
                        float o1 = sigf(ps1) * tanhf(cn1);
                        *(float2*)&new_state[gRow * 512 + n]       = make_float2(o0, o1);
                        *(float2*)&new_state[gRow * 512 + 256 + n] = make_float2(cn0, cn1);
                    }
                }
        } else {
            #pragma unroll
            for (int mt = 0; mt < 2; mt++)
                #pragma unroll
                for (int rh = 0; rh < 2; rh++) {
                    const long gRow = row0 + wm * 32 + mt * 16 + grp + rh * 8;
                    const int e = rh * 2;
                    #pragma unroll
                    for (int nt = 0; nt < 2; nt++) {
                        const int ncl = wn * 16 + nt * 8 + 2 * qid;
                        if (ni == 0) {
                            #pragma unroll
                            for (int g = 0; g < 4; g++)
                                *(float2*)&means[gRow * 256 + g * 64 + ncl] =
                                    make_float2(acc[g][mt][nt][e], acc[g][mt][nt][e + 1]);
                        } else if (ni == 1) {
                            #pragma unroll
                            for (int g = 0; g < 4; g++)
                                *(float2*)&devs[gRow * 256 + g * 64 + ncl] =
                                    make_float2(__expf(acc[g][mt][nt][e]),
                                                __expf(acc[g][mt][nt][e + 1]));
                        } else {
                            // softmax over the 4 heads (= 4 "gates") at same (row, t)
                            float ex[4][2], inv[2];
                            #pragma unroll
                            for (int j = 0; j < 2; j++) {
                                float v0 = acc[0][mt][nt][e + j], v1 = acc[1][mt][nt][e + j];
                                float v2 = acc[2][mt][nt][e + j], v3 = acc[3][mt][nt][e + j];
                                float m = fmaxf(fmaxf(v0, v1), fmaxf(v2, v3));
                                ex[0][j] = __expf(v0 - m); ex[1][j] = __expf(v1 - m);
                                ex[2][j] = __expf(v2 - m); ex[3][j] = __expf(v3 - m);
                                inv[j] = 1.0f / (ex[0][j] + ex[1][j] + ex[2][j] + ex[3][j]);
                            }
                            #pragma unroll
                            for (int g = 0; g < 4; g++)
                                *(float2*)&mult[gRow * 256 + g * 64 + ncl] =
                                    make_float2(ex[g][0] * inv[0], ex[g][1] * inv[1]);
                        }
                    }
                }
        }
    }
}

extern "C" void kernel_launch(void* const* d_in, const int* in_sizes, int n_in,
                              void* d_out, int out_size)
{
    const float* inp    = (const float*)d_in[0];
    const float* state1 = (const float*)d_in[1];
    const float* state2 = (const float*)d_in[2];
    const float* ffw    = (const float*)d_in[19];
    const float *l1w[4], *l1b[4], *l2w[4], *l2b[4];

    // Disambiguate input ordering by size: l1 weights are 320*256=81920,
    // l2 weights are 512*256=131072 elements.
    if (in_sizes[5] == 512 * 256) {
        // dict insertion order: (l1_wX, l1_bX, l2_wX, l2_bX) per gate X in f,k,i,s
        for (int g = 0; g < 4; g++) {
            l1w[g] = (const float*)d_in[3 + 4 * g];
            l1b[g] = (const float*)d_in[4 + 4 * g];
            l2w[g] = (const float*)d_in[5 + 4 * g];
            l2b[g] = (const float*)d_in[6 + 4 * g];
        }
    } else {
        // reference signature order: all l1 (w,b) pairs, then all l2 pairs
        for (int g = 0; g < 4; g++) {
            l1w[g] = (const float*)d_in[3 + 2 * g];
            l1b[g] = (const float*)d_in[4 + 2 * g];
            l2w[g] = (const float*)d_in[11 + 2 * g];
            l2b[g] = (const float*)d_in[12 + 2 * g];
        }
    }

    float* outp  = (float*)d_out;
    float* means = outp;
    float* devs  = outp + (size_t)BATCH * 256;
    float* mult  = outp + (size_t)BATCH * 512;
    float* ns1   = outp + (size_t)BATCH * 768;            // new_state1 [B,512]
    float* ns2   = ns1  + (size_t)BATCH * 512;            // new_state2 [B,512]

    const size_t sm1 = (size_t)(BM * (320 + 4) + 2 * WBUF) * 4;  // 156672 B
    const size_t sm2 = (size_t)(BM * (512 + 4) + 2 * WBUF) * 4;  // 205824 B
    const size_t sm3 = (size_t)(BM * (256 + 4) + 2 * WBUF) * 4;  // 140288 B
    cudaFuncSetAttribute(fused_kernel<0>, cudaFuncAttributeMaxDynamicSharedMemorySize, (int)sm2);
    cudaFuncSetAttribute(fused_kernel<1>, cudaFuncAttributeMaxDynamicSharedMemorySize, (int)sm3);

    const int grid = BATCH / BM;  // 512 blocks

    // Layer 1: X = [inp(64) | state1[:, :256]], K=320
    fused_kernel<0><<<grid, 256, sm1>>>(320, 4, 64, 0, 256,
        inp, 64, 64, state1,
        l1w[0], l1w[1], l1w[2], l1w[3],
        l1b[0], l1b[1], l1b[2], l1b[3],
        state1, ns1, nullptr, nullptr, nullptr);

    // Layer 2: X = [out1 (= ns1[:, :256]) | state2[:, :256]], K=512
    fused_kernel<0><<<grid, 256, sm2>>>(512, 4, 64, 0, 256,
        ns1, 256, 512, state2,
        l2w[0], l2w[1], l2w[2], l2w[3],
        l2b[0], l2b[1], l2b[2], l2b[3],
        state2, ns2, nullptr, nullptr, nullptr);

    // FF head: X = out2 (= ns2[:, :256]), K=256, N=768 in 3 iters of 4x64
    fused_kernel<1><<<grid, 256, sm3>>>(256, 3, 256, 64, 768,
        ns2, 256, 512, ns2,
        ffw, ffw, ffw, ffw,
        nullptr, nullptr, nullptr, nullptr,
        nullptr, nullptr, means, devs, mult);
}

// round 12
// speedup vs baseline: 1.6158x; 1.6158x over previous
#include <cuda_runtime.h>
#include <math.h>

#define BATCH 32768
#define BM 64

// Pre-packed tf32 weights: L1 (327680 w) | L2 (524288 w) | FF (196608 w) = 4 MB
__device__ unsigned g_wpack[1048576];

__device__ __forceinline__ unsigned f2tf32(float v) {
    unsigned r;
    asm("cvt.rna.tf32.f32 %0, %1;" : "=r"(r) : "f"(v));
    return r;
}

__device__ __forceinline__ void mma8(float* d, const unsigned* a, const unsigned* b) {
    asm volatile(
        "mma.sync.aligned.m16n8k8.row.col.f32.tf32.tf32.f32 "
        "{%0,%1,%2,%3}, {%4,%5,%6,%7}, {%8,%9}, {%0,%1,%2,%3};\n"
        : "+f"(d[0]), "+f"(d[1]), "+f"(d[2]), "+f"(d[3])
        : "r"(a[0]), "r"(a[1]), "r"(a[2]), "r"(a[3]), "r"(b[0]), "r"(b[1]));
}

__device__ __forceinline__ float sigf(float x) { return 1.0f / (1.0f + __expf(-x)); }

// Pack original fp32 weights -> tf32 (RNA), swizzled so that in smem each
// column block of 8 words is (k0,k4),(k1,k5),(k2,k6),(k3,k7): one LDS.64 per
// B-fragment. Layout: [ni][kb][g][n][8].
__global__ void pack_kernel(int dst_off,
                            const float* __restrict__ w0, const float* __restrict__ w1,
                            const float* __restrict__ w2, const float* __restrict__ w3,
                            int ldw, int BN, int NKB, int hstride, int nstep, int total)
{
    int t = blockIdx.x * 256 + threadIdx.x;
    if (t >= total) return;
    int idx = t;
    int e = idx & 1; idx >>= 1;
    int q = idx & 3; idx >>= 2;
    int n = idx % BN; idx /= BN;
    int g = idx & 3; idx >>= 2;
    int kb = idx % NKB;
    int ni = idx / NKB;
    const float* w = (g == 0) ? w0 : (g == 1) ? w1 : (g == 2) ? w2 : w3;
    int k = kb * 8 + q + e * 4;
    int col = ni * nstep + g * hstride + n;
    g_wpack[dst_off + t] = f2tf32(w[(long)k * ldw + col]);
}

// MODE 0: LSTM layer. 16 warps as 2(m)x8(n); warp tile m32 x n16 x 4 gates.
// MODE 1: FF head.    16 warps as 4(m)x4(n); warp tile m16 x n16 x 4 heads.
template <int MODE>
__global__ void __launch_bounds__(512, 1)
fused_kernel(int K, int NITER, int NKB, int wpk_off,
             const float* __restrict__ srcA, int KA, int lda,
             const float* __restrict__ srcB,
             const float* __restrict__ b0, const float* __restrict__ b1,
             const float* __restrict__ b2, const float* __restrict__ b3,
             const float* __restrict__ state_in, float* __restrict__ new_state,
             float* __restrict__ means, float* __restrict__ devs,
             float* __restrict__ mult)
{
    constexpr int BN  = (MODE == 0) ? 128 : 64;     // n-cols per gate per chunk
    constexpr int STG = 4 * BN * 8;                 // words per k8 stage (4 gates)
    constexpr int MT  = (MODE == 0) ? 2 : 1;        // m16 tiles per warp

    extern __shared__ unsigned sm[];
    const int XS = K + 8;                           // padded row stride (words)
    unsigned* xs  = sm;                             // X tile, pair-packed tf32
    unsigned* wsm = sm + BM * XS;                   // 4-stage W ring

    const int tid  = threadIdx.x;
    const int lane = tid & 31, wid = tid >> 5;
    const int wm = (MODE == 0) ? (wid >> 3) : (wid >> 2);
    const int wn = (MODE == 0) ? (wid & 7) : (wid & 3);
    const int grp = lane >> 2, qid = lane & 3;
    const long row0 = (long)blockIdx.x * BM;

    // ---- X tile: load fp32, cvt RNA, store (k,k+4)-pair-interleaved ----
    {
        const int r = tid >> 3, l8 = tid & 7;
        const long gr = row0 + r;
        for (int c = l8 * 4; c < K; c += 32) {
            float4 v = (c < KA) ? *(const float4*)(srcA + gr * lda + c)
                                : *(const float4*)(srcB + gr * 512 + (c - KA));
            unsigned* bp = xs + r * XS + ((c >> 3) << 3) + ((c >> 2) & 1);
            bp[0] = f2tf32(v.x); bp[2] = f2tf32(v.y);
            bp[4] = f2tf32(v.z); bp[6] = f2tf32(v.w);
        }
    }
    __syncthreads();

    for (int ni = 0; ni < NITER; ni++) {
        float acc[4][MT][2][4];
        #pragma unroll
        for (int g = 0; g < 4; g++)
            #pragma unroll
            for (int mt = 0; mt < MT; mt++)
                #pragma unroll
                for (int nt = 0; nt < 2; nt++)
                    #pragma unroll
                    for (int e = 0; e < 4; e++) acc[g][mt][nt][e] = 0.f;

        const unsigned* gw = g_wpack + wpk_off + (long)ni * NKB * STG;

        auto issue = [&](int s) {
            if (s < NKB) {
                const unsigned* src = gw + s * STG;
                unsigned* dst = wsm + (s & 3) * STG;
                if (MODE == 0) {
                    unsigned sa = (unsigned)__cvta_generic_to_shared(dst + tid * 8);
                    asm volatile("cp.async.cg.shared.global [%0], [%1], 16;"
                                 :: "r"(sa), "l"(src + tid * 8));
                    asm volatile("cp.async.cg.shared.global [%0], [%1], 16;"
                                 :: "r"(sa + 16), "l"(src + tid * 8 + 4));
                } else {
                    unsigned sa = (unsigned)__cvta_generic_to_shared(dst + tid * 4);
                    asm volatile("cp.async.cg.shared.global [%0], [%1], 16;"
                                 :: "r"(sa), "l"(src + tid * 4));
                }
            }
            asm volatile("cp.async.commit_group;");
        };

        issue(0); issue(1); issue(2);

        for (int kb = 0; kb < NKB; kb++) {
            asm volatile("cp.async.wait_group 2;");
            __syncthreads();
            const unsigned* wb = wsm + (kb & 3) * STG;

            unsigned a[MT][4];
            #pragma unroll
            for (int mt = 0; mt < MT; mt++) {
                const int row = wm * (16 * MT) + mt * 16 + grp;
                uint2 lo = *(const uint2*)(xs + row * XS + kb * 8 + qid * 2);
                uint2 hi = *(const uint2*)(xs + (row + 8) * XS + kb * 8 + qid * 2);
                a[mt][0] = lo.x; a[mt][1] = hi.x; a[mt][2] = lo.y; a[mt][3] = hi.y;
            }
            #pragma unroll
            for (int g = 0; g < 4; g++) {
                #pragma unroll
                for (int nt = 0; nt < 2; nt++) {
                    const int col = wn * 16 + nt * 8 + grp;
                    uint2 bb = *(const uint2*)(wb + (g * BN + col) * 8 + qid * 2);
                    unsigned bf[2] = {bb.x, bb.y};
                    #pragma unroll
                    for (int mt = 0; mt < MT; mt++) mma8(acc[g][mt][nt], a[mt], bf);
                }
            }
            issue(kb + 3);
        }

        // ---- epilogue ----
        if (MODE == 0) {
            #pragma unroll
            for (int mt = 0; mt < MT; mt++)
                #pragma unroll
                for (int rh = 0; rh < 2; rh++) {
                    const long gRow = row0 + wm * 32 + mt * 16 + grp + rh * 8;
                    const int e = rh * 2;
                    #pragma unroll
                    for (int nt = 0; nt < 2; nt++) {
                        const int n = ni * 128 + wn * 16 + nt * 8 + 2 * qid;
                        float2 vb;
                        vb = *(const float2*)&b0[n];
                        float pf0 = acc[0][mt][nt][e] + vb.x, pf1 = acc[0][mt][nt][e + 1] + vb.y;
                        vb = *(const float2*)&b1[n];
                        float pk0 = acc[1][mt][nt][e] + vb.x, pk1 = acc[1][mt][nt][e + 1] + vb.y;
                        vb = *(const float2*)&b2[n];
                        float pi0 = acc[2][mt][nt][e] + vb.x, pi1 = acc[2][mt][nt][e + 1] + vb.y;
                        vb = *(const float2*)&b3[n];
                        float ps0 = acc[3][mt][nt][e] + vb.x, ps1 = acc[3][mt][nt][e + 1] + vb.y;
                        const float2 cold = *(const float2*)&state_in[gRow * 512 + 256 + n];
                        float cn0 = sigf(pf0) * cold.x + sigf(pk0) * tanhf(pi0);
                        float cn1 = sigf(pf1) * cold.y + sigf(pk1) * tanhf(pi1);
                        float o0 = sigf(ps0) * tanhf(cn0);
                        float o1 = sigf(ps1) * tanhf(cn1);
                        *(float2*)&new_state[gRow * 512 + n]       = make_float2(o0, o1);
                        *(float2*)&new_state[gRow * 512 + 256 + n] = make_float2(cn0, cn1);
                    }
                }
        } else {
            #pragma unroll
            for (int rh = 0; rh < 2; rh++) {
                const long gRow = row0 + wm * 16 + grp + rh * 8;
                const int e = rh * 2;
                #pragma unroll
                for (int nt = 0; nt < 2; nt++) {
                    const int ncl = wn * 16 + nt * 8 + 2 * qid;
                    if (ni == 0) {
                        #pragma unroll
                        for (int g = 0; g < 4; g++)
                            *(float2*)&means[gRow * 256 + g * 64 + ncl] =
                                make_float2(acc[g][0][nt][e], acc[g][0][nt][e + 1]);
                    } else if (ni == 1) {
                        #pragma unroll
                        for (int g = 0; g < 4; g++)
                            *(float2*)&devs[gRow * 256 + g * 64 + ncl] =
                                make_float2(__expf(acc[g][0][nt][e]),
                                            __expf(acc[g][0][nt][e + 1]));
                    } else {
                        float ex[4][2], inv[2];
                        #pragma unroll
                        for (int j = 0; j < 2; j++) {
                            float v0 = acc[0][0][nt][e + j], v1 = acc[1][0][nt][e + j];
                            float v2 = acc[2][0][nt][e + j], v3 = acc[3][0][nt][e + j];
                            float m = fmaxf(fmaxf(v0, v1), fmaxf(v2, v3));
                            ex[0][j] = __expf(v0 - m); ex[1][j] = __expf(v1 - m);
                            ex[2][j] = __expf(v2 - m); ex[3][j] = __expf(v3 - m);
                            inv[j] = 1.0f / (ex[0][j] + ex[1][j] + ex[2][j] + ex[3][j]);
                        }
                        #pragma unroll
                        for (int g = 0; g < 4; g++)
                            *(float2*)&mult[gRow * 256 + g * 64 + ncl] =
                                make_float2(ex[g][0] * inv[0], ex[g][1] * inv[1]);
                    }
                }
            }
        }
    }
}

extern "C" void kernel_launch(void* const* d_in, const int* in_sizes, int n_in,
                              void* d_out, int out_size)
{
    const float* inp    = (const float*)d_in[0];
    const float* state1 = (const float*)d_in[1];
    const float* state2 = (const float*)d_in[2];
    const float* ffw    = (const float*)d_in[19];
    const float *l1w[4], *l1b[4], *l2w[4], *l2b[4];

    if (in_sizes[5] == 512 * 256) {
        for (int g = 0; g < 4; g++) {           // dict insertion order
            l1w[g] = (const float*)d_in[3 + 4 * g];
            l1b[g] = (const float*)d_in[4 + 4 * g];
            l2w[g] = (const float*)d_in[5 + 4 * g];
            l2b[g] = (const float*)d_in[6 + 4 * g];
        }
    } else {
        for (int g = 0; g < 4; g++) {           // signature order
            l1w[g] = (const float*)d_in[3 + 2 * g];
            l1b[g] = (const float*)d_in[4 + 2 * g];
            l2w[g] = (const float*)d_in[11 + 2 * g];
            l2b[g] = (const float*)d_in[12 + 2 * g];
        }
    }

    float* outp  = (float*)d_out;
    float* means = outp;
    float* devs  = outp + (size_t)BATCH * 256;
    float* mult  = outp + (size_t)BATCH * 512;
    float* ns1   = outp + (size_t)BATCH * 768;
    float* ns2   = ns1  + (size_t)BATCH * 512;

    // ---- weight pre-pack (tf32 + MMA-fragment swizzle) ----
    const int T1 = 2 * 40 * 4096;   // 327680
    const int T2 = 2 * 64 * 4096;   // 524288
    const int T3 = 3 * 32 * 2048;   // 196608
    pack_kernel<<<(T1 + 255) / 256, 256>>>(0,         l1w[0], l1w[1], l1w[2], l1w[3],
                                           256, 128, 40, 0, 128, T1);
    pack_kernel<<<(T2 + 255) / 256, 256>>>(T1,        l2w[0], l2w[1], l2w[2], l2w[3],
                                           256, 128, 64, 0, 128, T2);
    pack_kernel<<<(T3 + 255) / 256, 256>>>(T1 + T2,   ffw, ffw, ffw, ffw,
                                           768, 64, 32, 64, 256, T3);

    const size_t sm1 = (size_t)(BM * (320 + 8) + 4 * 4096) * 4;  // 149504
    const size_t sm2 = (size_t)(BM * (512 + 8) + 4 * 4096) * 4;  // 198656
    const size_t sm3 = (size_t)(BM * (256 + 8) + 4 * 2048) * 4;  // 100352
    cudaFuncSetAttribute(fused_kernel<0>, cudaFuncAttributeMaxDynamicSharedMemorySize, (int)sm2);
    cudaFuncSetAttribute(fused_kernel<1>, cudaFuncAttributeMaxDynamicSharedMemorySize, (int)sm3);

    const int grid = BATCH / BM;   // 512

    // Layer 1: X = [inp(64) | state1[:, :256]], K=320, NKB=40
    fused_kernel<0><<<grid, 512, sm1>>>(320, 2, 40, 0,
        inp, 64, 64, state1,
        l1b[0], l1b[1], l1b[2], l1b[3],
        state1, ns1, nullptr, nullptr, nullptr);

    // Layer 2: X = [out1 | state2[:, :256]], K=512, NKB=64
    fused_kernel<0><<<grid, 512, sm2>>>(512, 2, 64, T1,
        ns1, 256, 512, state2,
        l2b[0], l2b[1], l2b[2], l2b[3],
        state2, ns2, nullptr, nullptr, nullptr);

    // FF head: X = out2, K=256, NKB=32, 3 chunks of (4 heads x 64)
    fused_kernel<1><<<grid, 512, sm3>>>(256, 3, 32, T1 + T2,
        ns2, 256, 512, ns2,
        nullptr, nullptr, nullptr, nullptr,
        nullptr, nullptr, means, devs, mult);
}